// round 2
// baseline (speedup 1.0000x reference)
#include <cuda_runtime.h>

#define BB 24
#define DM 128
#define HH 8
#define DK 16
#define LL 512
#define HB (HH*BB)   // 192

// Scratch (allocation-free rule: __device__ globals)
__device__ float g_Q[HB*DK*LL];       // [hb][k][l]
__device__ float g_K[HB*DK*LL];
__device__ float g_V[HB*DK*LL];
__device__ float g_head[BB*DM*LL];    // [b][h*16+v][l]

// ---- packed f32x2 helpers (FFMA2: 2x fp32 throughput, PTX-only on sm_103a) ----
struct F2 { unsigned long long v; };
__device__ __forceinline__ F2 f2pack(float x, float y) {
    F2 r; asm("mov.b64 %0, {%1,%2};" : "=l"(r.v) : "f"(x), "f"(y)); return r;
}
__device__ __forceinline__ F2 f2dup(float x) { return f2pack(x, x); }
__device__ __forceinline__ void f2fma(F2& d, F2 a, F2 b) {
    asm("fma.rn.f32x2 %0, %1, %2, %0;" : "+l"(d.v) : "l"(a.v), "l"(b.v));
}
__device__ __forceinline__ void f2mul(F2& d, F2 a, F2 b) {
    asm("mul.rn.f32x2 %0, %1, %2;" : "=l"(d.v) : "l"(a.v), "l"(b.v));
}
__device__ __forceinline__ F2 f2add(F2 a, F2 b) {
    F2 r; asm("add.rn.f32x2 %0, %1, %2;" : "=l"(r.v) : "l"(a.v), "l"(b.v)); return r;
}
__device__ __forceinline__ float2 f2un(F2 a) {
    float2 r; asm("mov.b64 {%0,%1}, %2;" : "=f"(r.x), "=f"(r.y) : "l"(a.v)); return r;
}

// =====================================================================
// Kernel 1: QKV projection. One CTA per (h,b): [48x128] W @ [128x512] x
// =====================================================================
__global__ __launch_bounds__(256) void k_qkv(const float* __restrict__ x,
                                             const float* __restrict__ Wq,
                                             const float* __restrict__ Wk,
                                             const float* __restrict__ Wv)
{
    extern __shared__ float sm[];
    float* sW = sm;              // [48][128]
    float* sX = sm + 48*DM;      // [128][128]
    const int hb = blockIdx.x;   // hb = h*BB + b
    const int b  = hb % BB;
    const int t  = threadIdx.x;

    // Load 3 weight matrices (stacked 48 rows x 128)
    {
        const float4* srcQ = (const float4*)(Wq + (size_t)hb*DK*DM);
        const float4* srcK = (const float4*)(Wk + (size_t)hb*DK*DM);
        const float4* srcV = (const float4*)(Wv + (size_t)hb*DK*DM);
        float4* dst = (float4*)sW;
        for (int i = t; i < 1536; i += 256) {
            float4 v;
            if (i < 512)       v = srcQ[i];
            else if (i < 1024) v = srcK[i - 512];
            else               v = srcV[i - 1024];
            dst[i] = v;
        }
    }

    const int p4 = t & 31;       // l-quad
    const int rg = t >> 5;       // 0..7
    const float4* x4 = (const float4*)(x + (size_t)b*DM*LL);   // [128 rows][128 f4]

    for (int lt = 0; lt < 4; ++lt) {
        __syncthreads();
        float4* sX4 = (float4*)sX;
        for (int i = t; i < 4096; i += 256) {
            int d = i >> 5, lq = i & 31;
            sX4[i] = x4[d*128 + lt*32 + lq];
        }
        __syncthreads();

        F2 acc[6][2];
        #pragma unroll
        for (int j = 0; j < 6; ++j) { acc[j][0].v = 0ull; acc[j][1].v = 0ull; }

        for (int d4 = 0; d4 < 32; ++d4) {
            F2 xv[4][2];
            #pragma unroll
            for (int dd = 0; dd < 4; ++dd) {
                const ulonglong2 u = *(const ulonglong2*)&sX[(d4*4+dd)*128 + p4*4];
                xv[dd][0].v = u.x; xv[dd][1].v = u.y;
            }
            #pragma unroll
            for (int j = 0; j < 6; ++j) {
                const int r = rg + 8*j;
                const float4 w = *(const float4*)&sW[r*128 + d4*4];
                F2 w0 = f2dup(w.x), w1 = f2dup(w.y), w2 = f2dup(w.z), w3 = f2dup(w.w);
                f2fma(acc[j][0], w0, xv[0][0]); f2fma(acc[j][1], w0, xv[0][1]);
                f2fma(acc[j][0], w1, xv[1][0]); f2fma(acc[j][1], w1, xv[1][1]);
                f2fma(acc[j][0], w2, xv[2][0]); f2fma(acc[j][1], w2, xv[2][1]);
                f2fma(acc[j][0], w3, xv[3][0]); f2fma(acc[j][1], w3, xv[3][1]);
            }
        }

        #pragma unroll
        for (int j = 0; j < 6; ++j) {
            const int r = rg + 8*j;
            float* dst = (r < 16) ? g_Q : (r < 32 ? g_K : g_V);
            const int rr = r & 15;
            ulonglong2 u; u.x = acc[j][0].v; u.y = acc[j][1].v;
            *(ulonglong2*)&dst[((size_t)hb*DK + rr)*LL + lt*128 + p4*4] = u;
        }
    }
}

// =====================================================================
// Kernel 2: attention per (h,b). softmax over l (query axis), per column m.
// 512 threads: thread = (lg in {0,1}, m-pair). Online softmax + 2-way merge.
// =====================================================================
__global__ __launch_bounds__(512) void k_attn()
{
    extern __shared__ float sm[];
    unsigned long long* sQ2 = (unsigned long long*)sm;                       // [16*512] dup (q,q)
    float* sK               = sm + 2*DK*LL;                                  // [16*512]
    unsigned long long* sV2 = (unsigned long long*)(sm + 2*DK*LL + DK*LL);   // [16*512] dup (v,v)

    const int hb = blockIdx.x;
    const int b  = hb % BB;
    const int h  = hb / BB;
    const int t  = threadIdx.x;

    const float* gq = g_Q + (size_t)hb*DK*LL;
    const float* gk = g_K + (size_t)hb*DK*LL;
    const float* gv = g_V + (size_t)hb*DK*LL;

    for (int i = t; i < DK*LL; i += 512) {
        sQ2[i] = f2dup(gq[i]).v;
        sK[i]  = gk[i];
        sV2[i] = f2dup(gv[i]).v;
    }
    __syncthreads();

    const int p2 = t & 255;      // m-pair: columns 2*p2, 2*p2+1
    const int lg = t >> 8;       // 0..1 -> l range

    F2 kreg[16];
    #pragma unroll
    for (int k = 0; k < 16; ++k)
        kreg[k].v = *(const unsigned long long*)&sK[k*LL + 2*p2];

    F2 acc[16];
    #pragma unroll
    for (int k = 0; k < 16; ++k) acc[k].v = 0ull;
    float mx0 = -1e30f, mx1 = -1e30f, den0 = 0.f, den1 = 0.f;

    const int l0 = lg * 256;
    #pragma unroll 2
    for (int l = l0; l < l0 + 256; ++l) {
        // score pair: s = 0.25 * sum_k Q[k][l] * K[k][m]
        F2 sA; sA.v = 0ull;
        F2 sB; sB.v = 0ull;
        #pragma unroll
        for (int k = 0; k < 8; ++k) {
            F2 q; q.v = sQ2[k*LL + l];
            f2fma(sA, q, kreg[k]);
        }
        #pragma unroll
        for (int k = 8; k < 16; ++k) {
            F2 q; q.v = sQ2[k*LL + l];
            f2fma(sB, q, kreg[k]);
        }
        float2 sv = f2un(f2add(sA, sB));
        float sx = sv.x * 0.25f, sy = sv.y * 0.25f;

        // per-column online softmax (separate maxes to avoid underflow)
        float c0 = 1.f, c1 = 1.f;
        if (sx > mx0) { c0 = __expf(mx0 - sx); mx0 = sx; den0 *= c0; }
        if (sy > mx1) { c1 = __expf(mx1 - sy); mx1 = sy; den1 *= c1; }
        if (c0 != 1.f || c1 != 1.f) {
            F2 cc = f2pack(c0, c1);
            #pragma unroll
            for (int k = 0; k < 16; ++k) f2mul(acc[k], acc[k], cc);
        }
        float p0 = __expf(sx - mx0);
        float p1 = __expf(sy - mx1);
        den0 += p0; den1 += p1;

        F2 p = f2pack(p0, p1);
        #pragma unroll
        for (int k = 0; k < 16; ++k) {
            F2 v; v.v = sV2[k*LL + l];
            f2fma(acc[k], v, p);
        }
    }

    __syncthreads();   // done reading Q/K/V smem; reuse for partials
    float* sP = sm;    // [(m*2+lg)][18] : {max, den, acc[16]}
    {
        float* P0 = sP + (size_t)((2*p2)   * 2 + lg) * 18;
        float* P1 = sP + (size_t)((2*p2+1) * 2 + lg) * 18;
        P0[0] = mx0; P0[1] = den0;
        P1[0] = mx1; P1[1] = den1;
        #pragma unroll
        for (int k = 0; k < 16; ++k) {
            float2 a = f2un(acc[k]);
            P0[2+k] = a.x;
            P1[2+k] = a.y;
        }
    }
    __syncthreads();

    // merge the 2 l-partials per column and write head
    {
        const int m = t;  // 512 threads = 512 columns
        const float* A  = sP + (size_t)(m*2 + 0) * 18;
        const float* Bp = sP + (size_t)(m*2 + 1) * 18;
        float ma = A[0], mb = Bp[0];
        float M  = fmaxf(ma, mb);
        float ca = __expf(ma - M), cb = __expf(mb - M);
        float den = A[1]*ca + Bp[1]*cb;      // >= 1 always
        float inv = 1.0f / den;
        float* dst = g_head + ((size_t)b*DM + h*DK)*LL + m;
        #pragma unroll
        for (int v = 0; v < 16; ++v)
            dst[v*LL] = (A[2+v]*ca + Bp[2+v]*cb) * inv;
    }
}

// =====================================================================
// Kernel 3: out[b] = Wo[b] (128x128) @ head[b] (128x512)
// =====================================================================
__global__ __launch_bounds__(256) void k_out(const float* __restrict__ Wo,
                                             float* __restrict__ out)
{
    extern __shared__ float sm[];
    float* sW = sm;            // [128][128]
    float* sH = sm + DM*DM;    // [128][128]
    const int lt = blockIdx.x; // 0..3
    const int b  = blockIdx.y;
    const int t  = threadIdx.x;

    {
        const float4* w4 = (const float4*)(Wo + (size_t)b*DM*DM);
        float4* sW4 = (float4*)sW;
        for (int i = t; i < 4096; i += 256) sW4[i] = w4[i];
        const float4* h4 = (const float4*)(g_head + (size_t)b*DM*LL);
        float4* sH4 = (float4*)sH;
        for (int i = t; i < 4096; i += 256) {
            int d = i >> 5, lq = i & 31;
            sH4[i] = h4[d*128 + lt*32 + lq];
        }
    }
    __syncthreads();

    const int p4 = t & 31;
    const int rg = t >> 5;

    F2 acc[16][2];
    #pragma unroll
    for (int j = 0; j < 16; ++j) { acc[j][0].v = 0ull; acc[j][1].v = 0ull; }

    for (int d4 = 0; d4 < 32; ++d4) {
        F2 xv[4][2];
        #pragma unroll
        for (int dd = 0; dd < 4; ++dd) {
            const ulonglong2 u = *(const ulonglong2*)&sH[(d4*4+dd)*128 + p4*4];
            xv[dd][0].v = u.x; xv[dd][1].v = u.y;
        }
        #pragma unroll
        for (int j = 0; j < 16; ++j) {
            const int r = rg + 8*j;
            const float4 w = *(const float4*)&sW[r*128 + d4*4];
            F2 w0 = f2dup(w.x), w1 = f2dup(w.y), w2 = f2dup(w.z), w3 = f2dup(w.w);
            f2fma(acc[j][0], w0, xv[0][0]); f2fma(acc[j][1], w0, xv[0][1]);
            f2fma(acc[j][0], w1, xv[1][0]); f2fma(acc[j][1], w1, xv[1][1]);
            f2fma(acc[j][0], w2, xv[2][0]); f2fma(acc[j][1], w2, xv[2][1]);
            f2fma(acc[j][0], w3, xv[3][0]); f2fma(acc[j][1], w3, xv[3][1]);
        }
    }

    #pragma unroll
    for (int j = 0; j < 16; ++j) {
        const int r = rg + 8*j;
        ulonglong2 u; u.x = acc[j][0].v; u.y = acc[j][1].v;
        *(ulonglong2*)&out[((size_t)b*DM + r)*LL + lt*128 + p4*4] = u;
    }
}

// =====================================================================
extern "C" void kernel_launch(void* const* d_in, const int* in_sizes, int n_in,
                              void* d_out, int out_size)
{
    const float* x  = (const float*)d_in[0];
    const float* Wq = (const float*)d_in[1];
    const float* Wk = (const float*)d_in[2];
    const float* Wv = (const float*)d_in[3];
    const float* Wo = (const float*)d_in[4];
    float* out = (float*)d_out;

    cudaFuncSetAttribute(k_qkv,  cudaFuncAttributeMaxDynamicSharedMemorySize, 90112);
    cudaFuncSetAttribute(k_attn, cudaFuncAttributeMaxDynamicSharedMemorySize, 163840);
    cudaFuncSetAttribute(k_out,  cudaFuncAttributeMaxDynamicSharedMemorySize, 131072);

    k_qkv<<<HB, 256, 90112>>>(x, Wq, Wk, Wv);
    k_attn<<<HB, 512, 163840>>>();
    k_out<<<dim3(4, BB), 256, 131072>>>(Wo, out);
}

// round 5
// speedup vs baseline: 1.9647x; 1.9647x over previous
#include <cuda_runtime.h>
#include <cuda_fp16.h>
#include <cstdint>

#define BB 24
#define DM 128
#define HH 8
#define DK 16
#define LL 512
#define HB (HH*BB)   // 192

__device__ float g_Q[HB*DK*LL];       // [hb][k][l]
__device__ float g_K[HB*DK*LL];
__device__ float g_V[HB*DK*LL];
__device__ float g_head[BB*DM*LL];    // [b][h*16+v][l]

// ---- packed f32x2 helpers (k_qkv / k_out) ----
struct F2 { unsigned long long v; };
__device__ __forceinline__ F2 f2pack(float x, float y) {
    F2 r; asm("mov.b64 %0, {%1,%2};" : "=l"(r.v) : "f"(x), "f"(y)); return r;
}
__device__ __forceinline__ F2 f2dup(float x) { return f2pack(x, x); }
__device__ __forceinline__ void f2fma(F2& d, F2 a, F2 b) {
    asm("fma.rn.f32x2 %0, %1, %2, %0;" : "+l"(d.v) : "l"(a.v), "l"(b.v));
}

// ---- mma/ldmatrix helpers ----
__device__ __forceinline__ uint32_t smem_u32(const void* p) {
    uint32_t a;
    asm("{ .reg .u64 t; cvta.to.shared.u64 t, %1; cvt.u32.u64 %0, t; }" : "=r"(a) : "l"(p));
    return a;
}
__device__ __forceinline__ void ldsm4(uint32_t* r, uint32_t a) {
    asm volatile("ldmatrix.sync.aligned.m8n8.x4.shared.b16 {%0,%1,%2,%3}, [%4];"
        : "=r"(r[0]), "=r"(r[1]), "=r"(r[2]), "=r"(r[3]) : "r"(a));
}
__device__ __forceinline__ void mma_f16(float* d, const uint32_t* a, const uint32_t* b) {
    asm volatile("mma.sync.aligned.m16n8k16.row.col.f32.f16.f16.f32 "
        "{%0,%1,%2,%3}, {%4,%5,%6,%7}, {%8,%9}, {%0,%1,%2,%3};"
        : "+f"(d[0]), "+f"(d[1]), "+f"(d[2]), "+f"(d[3])
        : "r"(a[0]), "r"(a[1]), "r"(a[2]), "r"(a[3]), "r"(b[0]), "r"(b[1]));
}
__device__ __forceinline__ float ex2f(float x) {
    float r; asm("ex2.approx.f32 %0, %1;" : "=f"(r) : "f"(x)); return r;
}
// pack two floats into hi half2 + lo half2 (fp16 two-way split)
__device__ __forceinline__ void packhl(float p0, float p1, uint32_t& h, uint32_t& l) {
    __half2 hh = __floats2half2_rn(p0, p1);
    float2 f = __half22float2(hh);
    __half2 ll = __floats2half2_rn(p0 - f.x, p1 - f.y);
    h = *(uint32_t*)&hh; l = *(uint32_t*)&ll;
}

// =====================================================================
// Kernel 1: QKV projection (SIMT FFMA2, unchanged from R1 pass)
// =====================================================================
__global__ __launch_bounds__(256) void k_qkv(const float* __restrict__ x,
                                             const float* __restrict__ Wq,
                                             const float* __restrict__ Wk,
                                             const float* __restrict__ Wv)
{
    extern __shared__ float sm[];
    float* sW = sm;
    float* sX = sm + 48*DM;
    const int hb = blockIdx.x;
    const int b  = hb % BB;
    const int t  = threadIdx.x;

    {
        const float4* srcQ = (const float4*)(Wq + (size_t)hb*DK*DM);
        const float4* srcK = (const float4*)(Wk + (size_t)hb*DK*DM);
        const float4* srcV = (const float4*)(Wv + (size_t)hb*DK*DM);
        float4* dst = (float4*)sW;
        for (int i = t; i < 1536; i += 256) {
            float4 v;
            if (i < 512)       v = srcQ[i];
            else if (i < 1024) v = srcK[i - 512];
            else               v = srcV[i - 1024];
            dst[i] = v;
        }
    }

    const int p4 = t & 31;
    const int rg = t >> 5;
    const float4* x4 = (const float4*)(x + (size_t)b*DM*LL);

    for (int lt = 0; lt < 4; ++lt) {
        __syncthreads();
        float4* sX4 = (float4*)sX;
        for (int i = t; i < 4096; i += 256) {
            int d = i >> 5, lq = i & 31;
            sX4[i] = x4[d*128 + lt*32 + lq];
        }
        __syncthreads();

        F2 acc[6][2];
        #pragma unroll
        for (int j = 0; j < 6; ++j) { acc[j][0].v = 0ull; acc[j][1].v = 0ull; }

        for (int d4 = 0; d4 < 32; ++d4) {
            F2 xv[4][2];
            #pragma unroll
            for (int dd = 0; dd < 4; ++dd) {
                const ulonglong2 u = *(const ulonglong2*)&sX[(d4*4+dd)*128 + p4*4];
                xv[dd][0].v = u.x; xv[dd][1].v = u.y;
            }
            #pragma unroll
            for (int j = 0; j < 6; ++j) {
                const int r = rg + 8*j;
                const float4 w = *(const float4*)&sW[r*128 + d4*4];
                F2 w0 = f2dup(w.x), w1 = f2dup(w.y), w2 = f2dup(w.z), w3 = f2dup(w.w);
                f2fma(acc[j][0], w0, xv[0][0]); f2fma(acc[j][1], w0, xv[0][1]);
                f2fma(acc[j][0], w1, xv[1][0]); f2fma(acc[j][1], w1, xv[1][1]);
                f2fma(acc[j][0], w2, xv[2][0]); f2fma(acc[j][1], w2, xv[2][1]);
                f2fma(acc[j][0], w3, xv[3][0]); f2fma(acc[j][1], w3, xv[3][1]);
            }
        }

        #pragma unroll
        for (int j = 0; j < 6; ++j) {
            const int r = rg + 8*j;
            float* dst = (r < 16) ? g_Q : (r < 32 ? g_K : g_V);
            const int rr = r & 15;
            ulonglong2 u; u.x = acc[j][0].v; u.y = acc[j][1].v;
            *(ulonglong2*)&dst[((size_t)hb*DK + rr)*LL + lt*128 + p4*4] = u;
        }
    }
}

// =====================================================================
// Kernel 2: attention via mma.sync fp16 hi/lo split, flash-style.
// Grid 192 (hb), 512 threads = 16 warps x 32 m-rows.
// S[m,l] = sum_k K[k,m]Q[k,l]; softmax over l per row m;
// O[m,v] = sum_l P[m,l] V[v,l]; head[v][m] = O/den.
// =====================================================================
#define AT_QH 0
#define AT_QL 24576
#define AT_KH 49152
#define AT_KL 73728
#define AT_VH 98304
#define AT_VL 114944
#define AT_SMEM 131584

__global__ __launch_bounds__(512) void k_attn()
{
    extern __shared__ char smc[];
    const uint32_t su = smem_u32(smc);
    const int t = threadIdx.x, w = t >> 5, ln = t & 31;
    const int hb = blockIdx.x, b = hb % BB, h = hb / BB;

    __half* sQh = (__half*)(smc + AT_QH);   // [l][16] pitch 24 halves
    __half* sQl = (__half*)(smc + AT_QL);
    __half* sKh = (__half*)(smc + AT_KH);   // [m][16] pitch 24
    __half* sKl = (__half*)(smc + AT_KL);
    __half* sVh = (__half*)(smc + AT_VH);   // [v][l] pitch 520 halves
    __half* sVl = (__half*)(smc + AT_VL);

    const float* gq = g_Q + (size_t)hb * 8192;
    const float* gk = g_K + (size_t)hb * 8192;
    const float* gv = g_V + (size_t)hb * 8192;

    // stage: transpose Q,K to [seq][16] hi/lo; V kept [v][l] hi/lo
    for (int i = t; i < 8192; i += 512) {
        int k = i >> 9, l = i & 511;
        float q = gq[i];
        __half qh = __float2half_rn(q);
        sQh[l*24 + k] = qh; sQl[l*24 + k] = __float2half_rn(q - __half2float(qh));
        float kk = gk[i];
        __half khh = __float2half_rn(kk);
        sKh[l*24 + k] = khh; sKl[l*24 + k] = __float2half_rn(kk - __half2float(khh));
        float v = gv[i];
        __half vh = __float2half_rn(v);
        sVh[k*520 + l] = vh; sVl[k*520 + l] = __float2half_rn(v - __half2float(vh));
    }
    __syncthreads();

    const int rsel = ln & 15;
    const uint32_t csel = (uint32_t)(ln >> 4) * 16;

    // resident K A-fragments (this warp's 32 m-rows, 2 tiles of 16)
    uint32_t kh[2][4], kl[2][4];
    #pragma unroll
    for (int mt = 0; mt < 2; ++mt) {
        uint32_t ad = su + AT_KH + (uint32_t)((w*32 + mt*16 + rsel) * 48) + csel;
        ldsm4(kh[mt], ad);
        ldsm4(kl[mt], ad + (AT_KL - AT_KH));
    }

    float mx[2][2], dn[2][2], O[2][2][4];
    #pragma unroll
    for (int mt = 0; mt < 2; ++mt)
        #pragma unroll
        for (int j = 0; j < 2; ++j) {
            mx[mt][j] = -1e30f; dn[mt][j] = 0.f;
            #pragma unroll
            for (int r = 0; r < 4; ++r) O[mt][j][r] = 0.f;
        }

    const float C = 0.36067376022224085f;   // 0.25 * log2(e)

    for (int c = 0; c < 16; ++c) {
        // Q B-fragments (4 n-tiles of 8 l-cols), hi & lo
        uint32_t qbh[4][2], qbl[4][2];
        #pragma unroll
        for (int q = 0; q < 2; ++q) {
            uint32_t r4[4];
            uint32_t ad = su + AT_QH + (uint32_t)((c*32 + q*16 + rsel) * 48) + csel;
            ldsm4(r4, ad);
            qbh[2*q][0]=r4[0]; qbh[2*q][1]=r4[2]; qbh[2*q+1][0]=r4[1]; qbh[2*q+1][1]=r4[3];
            ldsm4(r4, ad + (AT_QL - AT_QH));
            qbl[2*q][0]=r4[0]; qbl[2*q][1]=r4[2]; qbl[2*q+1][0]=r4[1]; qbl[2*q+1][1]=r4[3];
        }

        // scores (3-term split)
        float s[2][4][4];
        #pragma unroll
        for (int mt = 0; mt < 2; ++mt)
            #pragma unroll
            for (int nt = 0; nt < 4; ++nt) {
                #pragma unroll
                for (int r = 0; r < 4; ++r) s[mt][nt][r] = 0.f;
                mma_f16(s[mt][nt], kh[mt], qbh[nt]);
                mma_f16(s[mt][nt], kh[mt], qbl[nt]);
                mma_f16(s[mt][nt], kl[mt], qbh[nt]);
            }

        // online softmax update
        #pragma unroll
        for (int mt = 0; mt < 2; ++mt) {
            float cA = -1e30f, cB = -1e30f;
            #pragma unroll
            for (int nt = 0; nt < 4; ++nt) {
                cA = fmaxf(cA, fmaxf(s[mt][nt][0], s[mt][nt][1]));
                cB = fmaxf(cB, fmaxf(s[mt][nt][2], s[mt][nt][3]));
            }
            cA = fmaxf(cA, __shfl_xor_sync(0xffffffffu, cA, 1));
            cA = fmaxf(cA, __shfl_xor_sync(0xffffffffu, cA, 2));
            cB = fmaxf(cB, __shfl_xor_sync(0xffffffffu, cB, 1));
            cB = fmaxf(cB, __shfl_xor_sync(0xffffffffu, cB, 2));
            float mA = fmaxf(mx[mt][0], cA), mB = fmaxf(mx[mt][1], cB);
            float sA = ex2f((mx[mt][0] - mA) * C), sB = ex2f((mx[mt][1] - mB) * C);
            mx[mt][0] = mA; mx[mt][1] = mB;
            dn[mt][0] *= sA; dn[mt][1] *= sB;
            #pragma unroll
            for (int vt = 0; vt < 2; ++vt) {
                O[mt][vt][0] *= sA; O[mt][vt][1] *= sA;
                O[mt][vt][2] *= sB; O[mt][vt][3] *= sB;
            }
            #pragma unroll
            for (int nt = 0; nt < 4; ++nt) {
                float p0 = ex2f((s[mt][nt][0] - mA) * C);
                float p1 = ex2f((s[mt][nt][1] - mA) * C);
                float p2 = ex2f((s[mt][nt][2] - mB) * C);
                float p3 = ex2f((s[mt][nt][3] - mB) * C);
                dn[mt][0] += p0 + p1; dn[mt][1] += p2 + p3;
                s[mt][nt][0] = p0; s[mt][nt][1] = p1;
                s[mt][nt][2] = p2; s[mt][nt][3] = p3;
            }
        }

        // O += P * V  (two k16 steps over this 32-l chunk)
        #pragma unroll
        for (int st = 0; st < 2; ++st) {
            uint32_t vbh[2][2], vbl[2][2], r4[4];
            uint32_t ad = su + AT_VH + (uint32_t)(rsel * 1040 + (c*32 + st*16) * 2) + csel;
            ldsm4(r4, ad);
            vbh[0][0]=r4[0]; vbh[0][1]=r4[2]; vbh[1][0]=r4[1]; vbh[1][1]=r4[3];
            ldsm4(r4, ad + (AT_VL - AT_VH));
            vbl[0][0]=r4[0]; vbl[0][1]=r4[2]; vbl[1][0]=r4[1]; vbl[1][1]=r4[3];

            #pragma unroll
            for (int mt = 0; mt < 2; ++mt) {
                uint32_t ah[4], al[4];
                packhl(s[mt][2*st][0],   s[mt][2*st][1],   ah[0], al[0]);
                packhl(s[mt][2*st][2],   s[mt][2*st][3],   ah[1], al[1]);
                packhl(s[mt][2*st+1][0], s[mt][2*st+1][1], ah[2], al[2]);
                packhl(s[mt][2*st+1][2], s[mt][2*st+1][3], ah[3], al[3]);
                #pragma unroll
                for (int vt = 0; vt < 2; ++vt) {
                    mma_f16(O[mt][vt], ah, vbh[vt]);
                    mma_f16(O[mt][vt], ah, vbl[vt]);
                    mma_f16(O[mt][vt], al, vbh[vt]);
                }
            }
        }
    }

    // reduce den across row-group lanes, write head
    #pragma unroll
    for (int mt = 0; mt < 2; ++mt)
        #pragma unroll
        for (int j = 0; j < 2; ++j) {
            dn[mt][j] += __shfl_xor_sync(0xffffffffu, dn[mt][j], 1);
            dn[mt][j] += __shfl_xor_sync(0xffffffffu, dn[mt][j], 2);
        }

    float* dst = g_head + ((size_t)b * DM + h * DK) * LL;
    #pragma unroll
    for (int mt = 0; mt < 2; ++mt)
        #pragma unroll
        for (int vt = 0; vt < 2; ++vt)
            #pragma unroll
            for (int r = 0; r < 4; ++r) {
                int m = w*32 + mt*16 + (ln >> 2) + ((r >> 1) & 1) * 8;
                int v = vt*8 + (ln & 3)*2 + (r & 1);
                dst[(size_t)v * LL + m] = O[mt][vt][r] / dn[mt][(r >> 1) & 1];
            }
}

// =====================================================================
// Kernel 3: out[b] = Wo[b] @ head[b] (SIMT FFMA2, unchanged)
// =====================================================================
__global__ __launch_bounds__(256) void k_out(const float* __restrict__ Wo,
                                             float* __restrict__ out)
{
    extern __shared__ float sm[];
    float* sW = sm;
    float* sH = sm + DM*DM;
    const int lt = blockIdx.x;
    const int b  = blockIdx.y;
    const int t  = threadIdx.x;

    {
        const float4* w4 = (const float4*)(Wo + (size_t)b*DM*DM);
        float4* sW4 = (float4*)sW;
        for (int i = t; i < 4096; i += 256) sW4[i] = w4[i];
        const float4* h4 = (const float4*)(g_head + (size_t)b*DM*LL);
        float4* sH4 = (float4*)sH;
        for (int i = t; i < 4096; i += 256) {
            int d = i >> 5, lq = i & 31;
            sH4[i] = h4[d*128 + lt*32 + lq];
        }
    }
    __syncthreads();

    const int p4 = t & 31;
    const int rg = t >> 5;

    F2 acc[16][2];
    #pragma unroll
    for (int j = 0; j < 16; ++j) { acc[j][0].v = 0ull; acc[j][1].v = 0ull; }

    for (int d4 = 0; d4 < 32; ++d4) {
        F2 xv[4][2];
        #pragma unroll
        for (int dd = 0; dd < 4; ++dd) {
            const ulonglong2 u = *(const ulonglong2*)&sH[(d4*4+dd)*128 + p4*4];
            xv[dd][0].v = u.x; xv[dd][1].v = u.y;
        }
        #pragma unroll
        for (int j = 0; j < 16; ++j) {
            const int r = rg + 8*j;
            const float4 w = *(const float4*)&sW[r*128 + d4*4];
            F2 w0 = f2dup(w.x), w1 = f2dup(w.y), w2 = f2dup(w.z), w3 = f2dup(w.w);
            f2fma(acc[j][0], w0, xv[0][0]); f2fma(acc[j][1], w0, xv[0][1]);
            f2fma(acc[j][0], w1, xv[1][0]); f2fma(acc[j][1], w1, xv[1][1]);
            f2fma(acc[j][0], w2, xv[2][0]); f2fma(acc[j][1], w2, xv[2][1]);
            f2fma(acc[j][0], w3, xv[3][0]); f2fma(acc[j][1], w3, xv[3][1]);
        }
    }

    #pragma unroll
    for (int j = 0; j < 16; ++j) {
        const int r = rg + 8*j;
        ulonglong2 u; u.x = acc[j][0].v; u.y = acc[j][1].v;
        *(ulonglong2*)&out[((size_t)b*DM + r)*LL + lt*128 + p4*4] = u;
    }
}

// =====================================================================
extern "C" void kernel_launch(void* const* d_in, const int* in_sizes, int n_in,
                              void* d_out, int out_size)
{
    const float* x  = (const float*)d_in[0];
    const float* Wq = (const float*)d_in[1];
    const float* Wk = (const float*)d_in[2];
    const float* Wv = (const float*)d_in[3];
    const float* Wo = (const float*)d_in[4];
    float* out = (float*)d_out;

    cudaFuncSetAttribute(k_qkv,  cudaFuncAttributeMaxDynamicSharedMemorySize, 90112);
    cudaFuncSetAttribute(k_attn, cudaFuncAttributeMaxDynamicSharedMemorySize, AT_SMEM);
    cudaFuncSetAttribute(k_out,  cudaFuncAttributeMaxDynamicSharedMemorySize, 131072);

    k_qkv<<<HB, 256, 90112>>>(x, Wq, Wk, Wv);
    k_attn<<<HB, 512, AT_SMEM>>>();
    k_out<<<dim3(4, BB), 256, 131072>>>(Wo, out);
}